// round 16
// baseline (speedup 1.0000x reference)
#include <cuda_runtime.h>
#include <cuda_bf16.h>
#include <cstdint>

// ---------------------------------------------------------------------------
// CopyNet pointer-generator mix — smem-free fused kernel (R15 + latency hiding).
//   out[b,t,v] = p_gen[b,t] * (v < V ? dist[b,t,v] : 0)
//              + (1 - p_gen[b,t]) * sum_{s: pointer[b,s]==v} alph[b,s,t]
//
// One CTA per (row, vocab-chunk), NCHUNK=8, 256 threads, no shared memory.
//   Prefetch: each thread loads its <=2 pointer values up front (latency
//             hidden behind the phase-A stream).
//   Phase A:  out = pg*dist (+ pad zeros), 2-deep batched LDG.128 pairs.
//   Phase B:  hits scatter into the just-written (L2-hot) lines via REDG.
// CTA exclusively owns its output range -> __syncthreads is sufficient order.
// ---------------------------------------------------------------------------

#define NCHUNK 8
#define TPB    256

__global__ __launch_bounds__(TPB, 8)
void copynet_stream_scatter_kernel(const float* __restrict__ dist,
                                   const float* __restrict__ p_gen,
                                   const float* __restrict__ alph,
                                   const int*   __restrict__ pointer,
                                   float* __restrict__ out,
                                   int V4, int Vext4, int chunk4,
                                   int L_DEC, int L_SRC)
{
    int row   = blockIdx.x / NCHUNK;           // b*L_DEC + t
    int chunk = blockIdx.x - row * NCHUNK;
    int b     = row / L_DEC;
    int t     = row - b * L_DEC;

    int lo = chunk * (chunk4 * 4);             // vocab range [lo, hi)
    int hi = lo + chunk4 * 4;

    float pg    = __ldg(&p_gen[row]);
    float one_m = 1.0f - pg;

    // Prefetch this thread's pointer values (<=2 when L_SRC <= 2*TPB).
    // Their latency is hidden behind the phase-A stream below.
    const int* prow = pointer + b * L_SRC;
    int s0 = threadIdx.x;
    int s1 = threadIdx.x + TPB;
    int p0 = (s0 < L_SRC) ? __ldg(&prow[s0]) : -1;
    int p1 = (s1 < L_SRC) ? __ldg(&prow[s1]) : -1;

    // Phase A: stream this chunk: out = pg*dist, zeros in the pad region.
    {
        int base4 = chunk * chunk4;
        const float4* src = reinterpret_cast<const float4*>(dist) + (size_t)row * V4;
        float4*       dst = reinterpret_cast<float4*>(out) + (size_t)row * Vext4 + base4;

        if (base4 + chunk4 <= V4) {
            // Chunk fully inside the vocab: branch-free, 2-deep pairs.
            int i = threadIdx.x;
            for (; i + TPB < chunk4; i += 2 * TPB) {
                float4 d0 = __ldg(&src[base4 + i]);
                float4 d1 = __ldg(&src[base4 + i + TPB]);
                d0.x *= pg; d0.y *= pg; d0.z *= pg; d0.w *= pg;
                d1.x *= pg; d1.y *= pg; d1.z *= pg; d1.w *= pg;
                dst[i]       = d0;
                dst[i + TPB] = d1;
            }
            if (i < chunk4) {
                float4 d = __ldg(&src[base4 + i]);
                d.x *= pg; d.y *= pg; d.z *= pg; d.w *= pg;
                dst[i] = d;
            }
        } else {
            // Boundary chunk: pad region gets zeros.
            for (int i = threadIdx.x; i < chunk4; i += TPB) {
                int g = base4 + i;
                float4 d = make_float4(0.f, 0.f, 0.f, 0.f);
                if (g < V4) {
                    d = __ldg(&src[g]);
                    d.x *= pg; d.y *= pg; d.z *= pg; d.w *= pg;
                }
                dst[i] = d;
            }
        }
    }

    // CTA-scope ordering: phase-A stores visible before phase-B RMWs.
    __syncthreads();

    // Phase B: scatter hits into the freshly written (L2-hot) chunk.
    {
        const float* arow = alph + ((size_t)b * L_SRC) * L_DEC + t;
        float* orow = out + (size_t)row * Vext4 * 4;

        if (p0 >= lo && p0 < hi) {
            float a = __ldg(&arow[(size_t)s0 * L_DEC]);
            atomicAdd(&orow[p0], one_m * a);
        }
        if (p1 >= lo && p1 < hi) {
            float a = __ldg(&arow[(size_t)s1 * L_DEC]);
            atomicAdd(&orow[p1], one_m * a);
        }
        // Generic remainder for L_SRC > 2*TPB (not taken for these shapes).
        for (int s = threadIdx.x + 2 * TPB; s < L_SRC; s += TPB) {
            int p = __ldg(&prow[s]);
            if (p >= lo && p < hi) {
                float a = __ldg(&arow[(size_t)s * L_DEC]);
                atomicAdd(&orow[p], one_m * a);
            }
        }
    }
}

// Fallback for odd shapes: full-row smem accumulator (proven correct).
__global__ void copynet_fused_scalar_kernel(const float* __restrict__ dist,
                                            const float* __restrict__ p_gen,
                                            const float* __restrict__ alph,
                                            const int*   __restrict__ pointer,
                                            float* __restrict__ out,
                                            int V, int Vext,
                                            int L_DEC, int L_SRC)
{
    extern __shared__ float srow[];
    int row = blockIdx.x;
    int b   = row / L_DEC;
    int t   = row - b * L_DEC;
    float pg = __ldg(&p_gen[row]);
    float one_m = 1.0f - pg;

    for (int i = threadIdx.x; i < Vext; i += blockDim.x)
        srow[i] = 0.f;
    __syncthreads();

    const float* arow = alph + ((size_t)b * L_SRC) * L_DEC + t;
    const int*   prow = pointer + b * L_SRC;
    for (int s = threadIdx.x; s < L_SRC; s += blockDim.x)
        atomicAdd(&srow[__ldg(&prow[s])], one_m * __ldg(&arow[(size_t)s * L_DEC]));
    __syncthreads();

    for (int i = threadIdx.x; i < Vext; i += blockDim.x) {
        float c = srow[i];
        if (i < V) c = fmaf(pg, __ldg(&dist[(size_t)row * V + i]), c);
        out[(size_t)row * Vext + i] = c;
    }
}

extern "C" void kernel_launch(void* const* d_in, const int* in_sizes, int n_in,
                              void* d_out, int out_size)
{
    // metadata order: dist_t, p_gen, alph_t, batch_vocab, pointer
    const float* dist    = (const float*)d_in[0];
    const float* p_gen   = (const float*)d_in[1];
    const float* alph    = (const float*)d_in[2];
    const int*   pointer = (const int*)d_in[4];
    float*       out     = (float*)d_out;

    int BT    = in_sizes[1];                 // B * L_DEC   (2048)
    int Vext  = in_sizes[3];                 // 32128
    int BS    = in_sizes[4];                 // B * L_SRC   (4096)
    int L_DEC = in_sizes[2] / BS;            // 256
    int B     = BT / L_DEC;                  // 8
    int L_SRC = BS / B;                      // 512
    int V     = in_sizes[0] / BT;            // 32000

    bool vec_ok = (V % 4 == 0) && (Vext % (4 * NCHUNK) == 0);

    if (vec_ok) {
        int V4     = V / 4;
        int Vext4  = Vext / 4;
        int chunk4 = Vext4 / NCHUNK;          // 1004 float4 per chunk
        copynet_stream_scatter_kernel<<<BT * NCHUNK, TPB>>>(
            dist, p_gen, alph, pointer, out, V4, Vext4, chunk4, L_DEC, L_SRC);
    } else {
        size_t smem_bytes = (size_t)Vext * sizeof(float);
        cudaFuncSetAttribute(copynet_fused_scalar_kernel,
                             cudaFuncAttributeMaxDynamicSharedMemorySize,
                             (int)smem_bytes);
        copynet_fused_scalar_kernel<<<BT, 1024, smem_bytes>>>(
            dist, p_gen, alph, pointer, out, V, Vext, L_DEC, L_SRC);
    }
}

// round 17
// speedup vs baseline: 1.1099x; 1.1099x over previous
#include <cuda_runtime.h>
#include <cuda_bf16.h>
#include <cstdint>

// ---------------------------------------------------------------------------
// CopyNet pointer-generator mix — smem-free fused kernel (R15 structure,
// NCHUNK=4 to halve the duplicated pointer scan).
//   out[b,t,v] = p_gen[b,t] * (v < V ? dist[b,t,v] : 0)
//              + (1 - p_gen[b,t]) * sum_{s: pointer[b,s]==v} alph[b,s,t]
//
// One CTA per (row, vocab-chunk), NCHUNK=4, 256 threads, NO shared memory.
//   Phase A: out = pg*dist (+ pad zeros), simple float4 loop (best measured).
//   Phase B: scan the row's pointers; hits atomicAdd into the just-written
//            (L2-hot) output lines. CTA exclusively owns its range, so
//            __syncthreads between phases is the only ordering needed.
// ---------------------------------------------------------------------------

#define NCHUNK 4
#define TPB    256

__global__ __launch_bounds__(TPB, 8)
void copynet_stream_scatter_kernel(const float* __restrict__ dist,
                                   const float* __restrict__ p_gen,
                                   const float* __restrict__ alph,
                                   const int*   __restrict__ pointer,
                                   float* __restrict__ out,
                                   int V4, int Vext4, int chunk4,
                                   int L_DEC, int L_SRC)
{
    int row   = blockIdx.x / NCHUNK;           // b*L_DEC + t
    int chunk = blockIdx.x - row * NCHUNK;
    int b     = row / L_DEC;
    int t     = row - b * L_DEC;

    int lo = chunk * (chunk4 * 4);             // vocab range [lo, hi)
    int hi = lo + chunk4 * 4;

    float pg    = __ldg(&p_gen[row]);
    float one_m = 1.0f - pg;

    // Phase A: stream this chunk: out = pg*dist, zeros in the pad region.
    {
        int base4 = chunk * chunk4;
        const float4* src = reinterpret_cast<const float4*>(dist) + (size_t)row * V4;
        float4*       dst = reinterpret_cast<float4*>(out) + (size_t)row * Vext4 + base4;

        if (base4 + chunk4 <= V4) {
            // Chunk fully inside the vocab: branch-free simple loop.
            for (int i = threadIdx.x; i < chunk4; i += TPB) {
                float4 d = __ldg(&src[base4 + i]);
                d.x *= pg; d.y *= pg; d.z *= pg; d.w *= pg;
                dst[i] = d;
            }
        } else {
            // Boundary chunk: pad region gets zeros.
            for (int i = threadIdx.x; i < chunk4; i += TPB) {
                int g = base4 + i;
                float4 d = make_float4(0.f, 0.f, 0.f, 0.f);
                if (g < V4) {
                    d = __ldg(&src[g]);
                    d.x *= pg; d.y *= pg; d.z *= pg; d.w *= pg;
                }
                dst[i] = d;
            }
        }
    }

    // CTA-scope ordering: phase-A stores visible before phase-B RMWs.
    __syncthreads();

    // Phase B: scatter the row's hits into the freshly written (L2-hot) chunk.
    {
        const float* arow = alph + ((size_t)b * L_SRC) * L_DEC + t;
        const int*   prow = pointer + b * L_SRC;
        float* orow = out + (size_t)row * Vext4 * 4;
        for (int s = threadIdx.x; s < L_SRC; s += TPB) {
            int p = __ldg(&prow[s]);
            if (p >= lo && p < hi) {
                float a = __ldg(&arow[(size_t)s * L_DEC]);
                atomicAdd(&orow[p], one_m * a);
            }
        }
    }
}

// Fallback for odd shapes: full-row smem accumulator (proven correct).
__global__ void copynet_fused_scalar_kernel(const float* __restrict__ dist,
                                            const float* __restrict__ p_gen,
                                            const float* __restrict__ alph,
                                            const int*   __restrict__ pointer,
                                            float* __restrict__ out,
                                            int V, int Vext,
                                            int L_DEC, int L_SRC)
{
    extern __shared__ float srow[];
    int row = blockIdx.x;
    int b   = row / L_DEC;
    int t   = row - b * L_DEC;
    float pg = __ldg(&p_gen[row]);
    float one_m = 1.0f - pg;

    for (int i = threadIdx.x; i < Vext; i += blockDim.x)
        srow[i] = 0.f;
    __syncthreads();

    const float* arow = alph + ((size_t)b * L_SRC) * L_DEC + t;
    const int*   prow = pointer + b * L_SRC;
    for (int s = threadIdx.x; s < L_SRC; s += blockDim.x)
        atomicAdd(&srow[__ldg(&prow[s])], one_m * __ldg(&arow[(size_t)s * L_DEC]));
    __syncthreads();

    for (int i = threadIdx.x; i < Vext; i += blockDim.x) {
        float c = srow[i];
        if (i < V) c = fmaf(pg, __ldg(&dist[(size_t)row * V + i]), c);
        out[(size_t)row * Vext + i] = c;
    }
}

extern "C" void kernel_launch(void* const* d_in, const int* in_sizes, int n_in,
                              void* d_out, int out_size)
{
    // metadata order: dist_t, p_gen, alph_t, batch_vocab, pointer
    const float* dist    = (const float*)d_in[0];
    const float* p_gen   = (const float*)d_in[1];
    const float* alph    = (const float*)d_in[2];
    const int*   pointer = (const int*)d_in[4];
    float*       out     = (float*)d_out;

    int BT    = in_sizes[1];                 // B * L_DEC   (2048)
    int Vext  = in_sizes[3];                 // 32128
    int BS    = in_sizes[4];                 // B * L_SRC   (4096)
    int L_DEC = in_sizes[2] / BS;            // 256
    int B     = BT / L_DEC;                  // 8
    int L_SRC = BS / B;                      // 512
    int V     = in_sizes[0] / BT;            // 32000

    bool vec_ok = (V % 4 == 0) && (Vext % (4 * NCHUNK) == 0);

    if (vec_ok) {
        int V4     = V / 4;
        int Vext4  = Vext / 4;
        int chunk4 = Vext4 / NCHUNK;          // 2008 float4 per chunk
        copynet_stream_scatter_kernel<<<BT * NCHUNK, TPB>>>(
            dist, p_gen, alph, pointer, out, V4, Vext4, chunk4, L_DEC, L_SRC);
    } else {
        size_t smem_bytes = (size_t)Vext * sizeof(float);
        cudaFuncSetAttribute(copynet_fused_scalar_kernel,
                             cudaFuncAttributeMaxDynamicSharedMemorySize,
                             (int)smem_bytes);
        copynet_fused_scalar_kernel<<<BT, 1024, smem_bytes>>>(
            dist, p_gen, alph, pointer, out, V, Vext, L_DEC, L_SRC);
    }
}